// round 15
// baseline (speedup 1.0000x reference)
#include <cuda_runtime.h>
#include <cstdint>

// BinaryLSTM: B=64, T=1024, D=128, H=512, C=2
// R15 = R13 + two-half software pipelining: each group's 16 batch rows split
// into two independent 8-row recurrences (A/B). While A computes step s, B's
// barrier+TMA exchange is in flight, and vice versa. k-split (2 threads/cell).

#define BB   64
#define TT   1024
#define DD   128
#define HH   512
#define G4   2048
#define NCLS 2
#define NCTA 128
#define NTHR 256
#define NGRP 4
#define GCTA 32
#define NBB  16
#define NBH  8        // batch rows per half
#define NJC  16
#define HROW 516
#define WTS  516
#define ZST  12       // zs row stride (floats): 48B -> conflict-free

// smem float offsets
#define HA_OFF   0
#define HB_OFF   (NBH*HROW)             // 4128
#define W_OFF    (2*NBH*HROW)           // 8256
#define ZS_OFF   (W_OFF + 64*WTS)       // 41280
#define HOUT_OFF (ZS_OFF + 128*ZST)     // 42816
#define MBAR_OFF (HOUT_OFF + 136)       // 42952 (byte 171808, 8-aligned)
#define SMEM_FLOATS (MBAR_OFF + 8)
#define SMEM_BYTES  (SMEM_FLOATS * 4)

// xz kernel (verbatim R13, proven)
#define XZ_TOK  32
#define XR      129
#define XZ_NTHR 256
#define XZ_SMEM_FLOATS (XZ_TOK*XR + DD*256)
#define XZ_SMEM_BYTES  (XZ_SMEM_FLOATS * 4)

typedef unsigned long long ull;

// ---- device scratch ----
__device__ float  g_h[2][BB][HH];
__device__ float  g_hs[(size_t)BB * TT * HH];
__device__ float4 g_xz4[(size_t)BB * TT * HH];   // [s][hc][bb] -> (i,f,g,o)
__device__ unsigned g_cnt[NGRP * 2 * 32];        // [grp][half], 128B apart
__device__ unsigned g_ph [NGRP * 2 * 32];

// ---- PTX helpers ----
__device__ __forceinline__ ull fma2(ull a, ull b, ull c) {
    ull d; asm("fma.rn.f32x2 %0, %1, %2, %3;" : "=l"(d) : "l"(a), "l"(b), "l"(c));
    return d;
}
__device__ __forceinline__ ull dup2(float x) {
    ull d; asm("mov.b64 %0, {%1, %1};" : "=l"(d) : "f"(x)); return d;
}
__device__ __forceinline__ ull pk2(float lo, float hi) {
    ull d; asm("mov.b64 %0, {%1, %2};" : "=l"(d) : "f"(lo), "f"(hi)); return d;
}
__device__ __forceinline__ float hadd2(ull v) {
    float lo, hi; asm("mov.b64 {%0, %1}, %2;" : "=f"(lo), "=f"(hi) : "l"(v));
    return lo + hi;
}
__device__ __forceinline__ uint32_t sa(const void* p) {
    return (uint32_t)__cvta_generic_to_shared(p);
}
__device__ __forceinline__ void mbar_wait(uint32_t mbar, unsigned parity) {
    asm volatile(
        "{\n\t.reg .pred P1;\n\t"
        "WAIT_%=:\n\t"
        "mbarrier.try_wait.parity.acquire.cta.shared::cta.b64 P1, [%0], %1;\n\t"
        "@P1 bra.uni DONE_%=;\n\t"
        "bra.uni WAIT_%=;\n\t"
        "DONE_%=:\n\t}"
        :: "r"(mbar), "r"(parity) : "memory");
}
__device__ __forceinline__ unsigned atom_add_acqrel_gpu(unsigned* p, unsigned v) {
    unsigned old;
    asm volatile("atom.add.acq_rel.gpu.global.u32 %0, [%1], %2;"
                 : "=r"(old) : "l"(p), "r"(v) : "memory");
    return old;
}
__device__ __forceinline__ void st_release_gpu(unsigned* p, unsigned v) {
    asm volatile("st.release.gpu.global.u32 [%0], %1;" :: "l"(p), "r"(v) : "memory");
}
__device__ __forceinline__ unsigned ld_acquire_gpu(const unsigned* p) {
    unsigned v;
    asm volatile("ld.acquire.gpu.global.u32 %0, [%1];" : "=r"(v) : "l"(p) : "memory");
    return v;
}
// tid0-only: arrive on a (counter, phase) pair; release when 32nd arrival.
__device__ __forceinline__ void bar_arrive(int idx, unsigned target) {
    unsigned old = atom_add_acqrel_gpu(&g_cnt[idx * 32], 1u);
    if ((old & (GCTA - 1u)) == GCTA - 1u)
        st_release_gpu(&g_ph[idx * 32], target);
}
__device__ __forceinline__ void bar_poll(int idx, unsigned target) {
    while ((int)(ld_acquire_gpu(&g_ph[idx * 32]) - target) < 0) { }
}
// stage one half (8 rows x 2KB) via bulk-async; completion -> mbar
__device__ __forceinline__ void tma_half(uint32_t mbar, uint32_t dst, const float* src) {
    asm volatile("mbarrier.arrive.expect_tx.shared.b64 _, [%0], %1;"
                 :: "r"(mbar), "r"(16384u) : "memory");
    #pragma unroll
    for (int rr = 0; rr < NBH; ++rr)
        asm volatile(
            "cp.async.bulk.shared::cta.global.mbarrier::complete_tx::bytes "
            "[%0], [%1], %2, [%3];"
            :: "r"(dst + (unsigned)(rr * HROW * 4)),
               "l"((const char*)src + rr * (HH * 4)), "r"(2048u), "r"(mbar)
            : "memory");
}

__device__ __forceinline__ float fast_sigmoid(float z) {
    return 1.f / (1.f + __expf(-z));
}
__device__ __forceinline__ float fast_tanh(float z) {
    float az = fabsf(z);
    float e  = __expf(-2.f * az);
    float t  = (1.f - e) / (1.f + e);
    return copysignf(t, z);
}

// partial dot for one half: thread (r = u&7, j = u>>3, kh) over 256 k.
__device__ __forceinline__ void half_partials(
    const float* hr, const float* w0, const float* w1,
    const float* w2, const float* w3,
    ull a0, ull a1, ull a2, ull a3, float* zrow, int kh)
{
    #pragma unroll 4
    for (int k = 0; k < 256; k += 8) {
        ulonglong2 hA = *(const ulonglong2*)(hr + k);
        ulonglong2 hB = *(const ulonglong2*)(hr + k + 4);
        ulonglong2 wa, wb;
        wa = *(const ulonglong2*)(w0 + k); wb = *(const ulonglong2*)(w0 + k + 4);
        a0 = fma2(hA.x, wa.x, a0); a0 = fma2(hA.y, wa.y, a0);
        a0 = fma2(hB.x, wb.x, a0); a0 = fma2(hB.y, wb.y, a0);
        wa = *(const ulonglong2*)(w1 + k); wb = *(const ulonglong2*)(w1 + k + 4);
        a1 = fma2(hA.x, wa.x, a1); a1 = fma2(hA.y, wa.y, a1);
        a1 = fma2(hB.x, wb.x, a1); a1 = fma2(hB.y, wb.y, a1);
        wa = *(const ulonglong2*)(w2 + k); wb = *(const ulonglong2*)(w2 + k + 4);
        a2 = fma2(hA.x, wa.x, a2); a2 = fma2(hA.y, wa.y, a2);
        a2 = fma2(hB.x, wb.x, a2); a2 = fma2(hB.y, wb.y, a2);
        wa = *(const ulonglong2*)(w3 + k); wb = *(const ulonglong2*)(w3 + k + 4);
        a3 = fma2(hA.x, wa.x, a3); a3 = fma2(hA.y, wa.y, a3);
        a3 = fma2(hB.x, wb.x, a3); a3 = fma2(hB.y, wb.y, a3);
    }
    *(float4*)(zrow + kh * 4) =
        make_float4(hadd2(a0), hadd2(a1), hadd2(a2), hadd2(a3));
}

// ---------------------------------------------------------------------------
// xz kernel (VERBATIM R13, proven)
// ---------------------------------------------------------------------------
__global__ void __launch_bounds__(XZ_NTHR, 1)
xz_kernel(const float* __restrict__ x,
          const float* __restrict__ Wx,
          const float* __restrict__ bias)
{
    extern __shared__ float sm[];
    float* x_s = sm;
    float* w_s = sm + XZ_TOK * XR;

    const int tid  = threadIdx.x;
    const int tokT = blockIdx.x >> 3;
    const int colT = blockIdx.x & 7;
    const int cg   = tid >> 5;
    const int tt   = tid & 31;

    for (int c = tid; c < XZ_TOK * DD; c += XZ_NTHR) {
        int t = c >> 7, d = c & (DD - 1);
        int token = tokT * XZ_TOK + t;
        int bb = token & (BB - 1), s = token >> 6;
        x_s[t * XR + d] = x[((size_t)bb * TT + s) * DD + d];
    }
    for (int c = tid; c < DD * 256; c += XZ_NTHR) {
        int d = c >> 8, cl = c & 255;
        w_s[c] = Wx[(size_t)d * G4 + (cl >> 6) * HH + colT * 64 + (cl & 63)];
    }
    __syncthreads();

    const int hc0 = colT * 64 + cg * 8;
    ull acc[4][4];
    #pragma unroll
    for (int g = 0; g < 4; ++g)
        #pragma unroll
        for (int p = 0; p < 4; ++p)
            acc[g][p] = *(const ull*)(bias + g * HH + hc0 + 2 * p);

    const float* xr = x_s + tt * XR;
    #pragma unroll 4
    for (int d = 0; d < DD; ++d) {
        ull xd = dup2(xr[d]);
        const ull* wr = (const ull*)(w_s + d * 256 + cg * 8);
        #pragma unroll
        for (int g = 0; g < 4; ++g) {
            const ull* wg2 = wr + g * 32;
            acc[g][0] = fma2(xd, wg2[0], acc[g][0]);
            acc[g][1] = fma2(xd, wg2[1], acc[g][1]);
            acc[g][2] = fma2(xd, wg2[2], acc[g][2]);
            acc[g][3] = fma2(xd, wg2[3], acc[g][3]);
        }
    }
    int token = tokT * XZ_TOK + tt;
    int bb = token & (BB - 1), s = token >> 6;
    float v[4][8];
    #pragma unroll
    for (int g = 0; g < 4; ++g)
        #pragma unroll
        for (int p = 0; p < 4; ++p) {
            float lo, hi;
            asm("mov.b64 {%0, %1}, %2;" : "=f"(lo), "=f"(hi) : "l"(acc[g][p]));
            v[g][2 * p] = lo; v[g][2 * p + 1] = hi;
        }
    #pragma unroll
    for (int ii = 0; ii < 8; ++ii)
        g_xz4[((size_t)s * HH + hc0 + ii) * BB + bb] =
            make_float4(v[0][ii], v[1][ii], v[2][ii], v[3][ii]);
}

// ---------------------------------------------------------------------------
// Pipelined group recurrence
// ---------------------------------------------------------------------------
__global__ void __launch_bounds__(NTHR, 1)
group_lstm_kernel(const float* __restrict__ Wh,
                  float* __restrict__ d_cost)
{
    extern __shared__ float sm[];
    float* h_sA = sm + HA_OFF;                 // [8][HROW]
    float* h_sB = sm + HB_OFF;                 // [8][HROW]
    float* whsT = sm + W_OFF;                  // [64][WTS]
    float* zs   = sm + ZS_OFF;                 // [128][ZST]
    float* hout = sm + HOUT_OFF;               // [8][17]
    const uint32_t mbarA = sa(sm + MBAR_OFF);
    const uint32_t mbarB = sa(sm + MBAR_OFF + 2);

    const int tid = threadIdx.x;
    const int cta = blockIdx.x;
    const int grp = cta >> 5;
    const int gc  = cta & 31;
    const int kh  = tid >> 7;                  // k-half
    const int u   = tid & 127;                 // cell within half
    const int r   = u & 7;                     // local batch row
    const int j   = u >> 3;                    // local h-col
    const int idxA = grp * 2, idxB = grp * 2 + 1;

    if (cta == 0 && tid == 0) *d_cost = 0.f;

    // stationary weights (proven layout)
    for (int i = tid; i < 64 * HH; i += NTHR) {
        int cc = i >> 9, k = i & (HH - 1);
        whsT[cc * WTS + k] = Wh[(size_t)k * G4 + (cc >> 4) * HH + gc * NJC + (cc & 15)];
    }
    // h0 zeros (every cell of group covered: 16 rows x 16 cols = 256 threads)
    __stcg(&g_h[0][grp * NBB + (tid & 15)][gc * NJC + (tid >> 4)], 0.f);

    unsigned pbA = 0, pbB = 0;
    if (tid == 0) {
        pbA = ld_acquire_gpu(&g_ph[idxA * 32]);
        pbB = ld_acquire_gpu(&g_ph[idxB * 32]);
        asm volatile("mbarrier.init.shared.b64 [%0], %1;" :: "r"(mbarA), "r"(1u) : "memory");
        asm volatile("mbarrier.init.shared.b64 [%0], %1;" :: "r"(mbarB), "r"(1u) : "memory");
    }
    __syncthreads();
    // prologue full barrier on A-counter: h0 visible group-wide
    if (tid == 0) {
        bar_arrive(idxA, pbA + 1);
        bar_poll(idxA, pbA + 1);
        tma_half(mbarA, sa(h_sA), &g_h[0][grp * NBB][0]);
        tma_half(mbarB, sa(h_sB), &g_h[0][grp * NBB + NBH][0]);
    }
    __syncthreads();

    const int k0 = kh << 8;
    const float* hrA = h_sA + r * HROW + k0;
    const float* hrB = h_sB + r * HROW + k0;
    const float* w0 = whsT + (0 * NJC + j) * WTS + k0;
    const float* w1 = whsT + (1 * NJC + j) * WTS + k0;
    const float* w2 = whsT + (2 * NJC + j) * WTS + k0;
    const float* w3 = whsT + (3 * NJC + j) * WTS + k0;
    float* zrow = zs + u * ZST;

    const int hcg = gc * NJC + j;              // gate-thread h-col (t<128)
    const int bbA = grp * NBB + r;
    const int bbB = grp * NBB + NBH + r;
    const int wb_r = tid >> 4, wb_h = tid & 15; // writeback map (t<128)

    float c_A = 0.f, c_B = 0.f;
    float4 xzA = make_float4(0,0,0,0), xzB = xzA, xzA_n, xzB_n;
    if (tid < 128) {
        xzA = g_xz4[((size_t)0 * HH + hcg) * BB + bbA];
        xzB = g_xz4[((size_t)0 * HH + hcg) * BB + bbB];
    }

    for (int s = 0; s < TT; ++s) {
        const int cur = s & 1, nxt = cur ^ 1;

        // ================= HALF A =================
        mbar_wait(mbarA, (unsigned)cur);
        if (tid == 0 && s > 0) {               // restage B(s); lands during compute A
            bar_poll(idxB, pbB + (unsigned)s);
            tma_half(mbarB, sa(h_sB), &g_h[cur][grp * NBB + NBH][0]);
        }
        if (tid < 128 && s + 1 < TT) {         // prefetch next xz
            xzA_n = g_xz4[((size_t)(s + 1) * HH + hcg) * BB + bbA];
            xzB_n = g_xz4[((size_t)(s + 1) * HH + hcg) * BB + bbB];
        }
        {
            ull a0 = 0, a1 = 0, a2 = 0, a3 = 0;
            if (kh == 0) { a0 = pk2(xzA.x, 0.f); a1 = pk2(xzA.y, 0.f);
                           a2 = pk2(xzA.z, 0.f); a3 = pk2(xzA.w, 0.f); }
            half_partials(hrA, w0, w1, w2, w3, a0, a1, a2, a3, zrow, kh);
        }
        __syncthreads();
        if (tid < 128) {
            float4 p0 = *(const float4*)(zs + tid * ZST);
            float4 p1 = *(const float4*)(zs + tid * ZST + 4);
            float zi = p0.x + p1.x, zf = p0.y + p1.y;
            float zg = p0.z + p1.z, zo = p0.w + p1.w;
            float ig = fast_sigmoid(zi), fg = fast_sigmoid(zf);
            float gg = fast_tanh(zg),    og = fast_sigmoid(zo);
            c_A = fg * c_A + ig * gg;
            hout[r * 17 + j] = og * fast_tanh(c_A);
        }
        __syncthreads();
        if (tid < 128) {
            float val = hout[wb_r * 17 + wb_h];
            __stcg(&g_h[nxt][grp * NBB + wb_r][gc * NJC + wb_h], val);
            g_hs[((size_t)(grp * NBB + wb_r) * TT + s) * HH + gc * NJC + wb_h] = val;
        }
        __syncthreads();
        if (tid == 0) bar_arrive(idxA, pbA + 2 + (unsigned)s);

        // ================= HALF B =================
        mbar_wait(mbarB, (unsigned)cur);
        if (tid == 0 && s + 1 < TT) {          // restage A(s+1); lands during compute B
            bar_poll(idxA, pbA + 2 + (unsigned)s);
            tma_half(mbarA, sa(h_sA), &g_h[nxt][grp * NBB][0]);
        }
        {
            ull a0 = 0, a1 = 0, a2 = 0, a3 = 0;
            if (kh == 0) { a0 = pk2(xzB.x, 0.f); a1 = pk2(xzB.y, 0.f);
                           a2 = pk2(xzB.z, 0.f); a3 = pk2(xzB.w, 0.f); }
            half_partials(hrB, w0, w1, w2, w3, a0, a1, a2, a3, zrow, kh);
        }
        __syncthreads();
        if (tid < 128) {
            float4 p0 = *(const float4*)(zs + tid * ZST);
            float4 p1 = *(const float4*)(zs + tid * ZST + 4);
            float zi = p0.x + p1.x, zf = p0.y + p1.y;
            float zg = p0.z + p1.z, zo = p0.w + p1.w;
            float ig = fast_sigmoid(zi), fg = fast_sigmoid(zf);
            float gg = fast_tanh(zg),    og = fast_sigmoid(zo);
            c_B = fg * c_B + ig * gg;
            hout[r * 17 + j] = og * fast_tanh(c_B);
        }
        __syncthreads();
        if (tid < 128) {
            float val = hout[wb_r * 17 + wb_h];
            __stcg(&g_h[nxt][grp * NBB + NBH + wb_r][gc * NJC + wb_h], val);
            g_hs[((size_t)(grp * NBB + NBH + wb_r) * TT + s) * HH + gc * NJC + wb_h] = val;
        }
        __syncthreads();
        if (tid == 0) bar_arrive(idxB, pbB + 1 + (unsigned)s);

        xzA = xzA_n; xzB = xzB_n;
    }
}

// Head (VERBATIM, proven)
__global__ void __launch_bounds__(256)
head_kernel(const int* __restrict__ labels,
            const float* __restrict__ Wo,
            const float* __restrict__ bo,
            float* __restrict__ out,
            float* __restrict__ d_cost)
{
    __shared__ float part[8];
    int warp = threadIdx.x >> 5, lane = threadIdx.x & 31;
    int bt   = blockIdx.x * 8 + warp;
    const float* hrow = g_hs + (size_t)bt * HH;

    float s0 = 0.f, s1 = 0.f;
    #pragma unroll 4
    for (int k = lane; k < HH; k += 32) {
        float  h = hrow[k];
        float2 w = ((const float2*)Wo)[k];
        s0 += h * w.x; s1 += h * w.y;
    }
    #pragma unroll
    for (int off = 16; off; off >>= 1) {
        s0 += __shfl_xor_sync(0xffffffffu, s0, off);
        s1 += __shfl_xor_sync(0xffffffffu, s1, off);
    }
    if (lane == 0) {
        float l0 = s0 + bo[0], l1 = s1 + bo[1];
        float m  = fmaxf(l0, l1);
        float e0 = __expf(l0 - m), e1 = __expf(l1 - m);
        float Z  = e0 + e1;
        float inv = 1.f / Z;
        ((float2*)out)[bt] = make_float2(e0 * inv, e1 * inv);
        int lab = labels[bt];
        float llab = lab ? l1 : l0;
        part[warp] = -(llab - m - __logf(Z));
    }
    __syncthreads();
    if (threadIdx.x == 0) {
        float sum = 0.f;
        #pragma unroll
        for (int w = 0; w < 8; ++w) sum += part[w];
        atomicAdd(d_cost, sum * (1.f / (float)(BB * TT)));
    }
}

extern "C" void kernel_launch(void* const* d_in, const int* in_sizes, int n_in,
                              void* d_out, int out_size)
{
    (void)in_sizes; (void)n_in; (void)out_size;
    const float* x      = (const float*)d_in[0];
    const int*   labels = (const int*)  d_in[1];
    const float* Wx     = (const float*)d_in[2];
    const float* Wh     = (const float*)d_in[3];
    const float* b      = (const float*)d_in[4];
    const float* Wo     = (const float*)d_in[5];
    const float* bo     = (const float*)d_in[6];
    float* out    = (float*)d_out;
    float* d_cost = out + (size_t)BB * TT * NCLS;

    cudaFuncSetAttribute(xz_kernel,
                         cudaFuncAttributeMaxDynamicSharedMemorySize, XZ_SMEM_BYTES);
    cudaFuncSetAttribute(group_lstm_kernel,
                         cudaFuncAttributeMaxDynamicSharedMemorySize, SMEM_BYTES);

    xz_kernel<<<(BB * TT / XZ_TOK) * 8, XZ_NTHR, XZ_SMEM_BYTES>>>(x, Wx, b);
    group_lstm_kernel<<<NCTA, NTHR, SMEM_BYTES>>>(Wh, d_cost);
    head_kernel<<<(BB * TT) / 8, 256>>>(labels, Wo, bo, out, d_cost);
}

// round 16
// speedup vs baseline: 1.1617x; 1.1617x over previous
#include <cuda_runtime.h>
#include <cstdint>

// BinaryLSTM: B=64, T=1024, D=128, H=512, C=2
// R16 = R13 + warp-specialized dual recurrence: warps 0-3 run rows 0-7 of the
// group, warps 4-7 run rows 8-15, as fully independent pipelines (own mbar,
// own TMA, own 32-CTA barrier, named bar.sync). Latency of one half hides
// under compute of the other. No k-split, gates in-register (R13-proven math).

#define BB   64
#define TT   1024
#define DD   128
#define HH   512
#define G4   2048
#define NCLS 2
#define NCTA 128
#define NTHR 256
#define NGRP 4
#define GCTA 32
#define NBH  8        // rows per half
#define NJC  16       // h-cols per CTA
#define HROW 516
#define WTS  516

// smem float offsets
#define HA_OFF    0
#define HB_OFF    (NBH*HROW)               // 4128
#define W_OFF     (2*NBH*HROW)             // 8256
#define HOUTA_OFF (W_OFF + 64*WTS)         // 41280
#define HOUTB_OFF (HOUTA_OFF + 136)        // 41416
#define MBAR_OFF  (HOUTB_OFF + 136)        // 41552 (byte 166208, 8-aligned)
#define SMEM_FLOATS (MBAR_OFF + 4)
#define SMEM_BYTES  (SMEM_FLOATS * 4)

// xz kernel (verbatim R13, proven)
#define XZ_TOK  32
#define XR      129
#define XZ_NTHR 256
#define XZ_SMEM_FLOATS (XZ_TOK*XR + DD*256)
#define XZ_SMEM_BYTES  (XZ_SMEM_FLOATS * 4)

typedef unsigned long long ull;

// ---- device scratch ----
__device__ float  g_h[2][BB][HH];
__device__ float  g_hs[(size_t)BB * TT * HH];
__device__ float4 g_xz4[(size_t)BB * TT * HH];   // [s][hc][bb] -> (i,f,g,o)
__device__ unsigned g_cnt[NGRP * 2 * 32];        // [grp*2+half], 128B apart
__device__ unsigned g_ph [NGRP * 2 * 32];

// ---- PTX helpers ----
__device__ __forceinline__ ull fma2(ull a, ull b, ull c) {
    ull d; asm("fma.rn.f32x2 %0, %1, %2, %3;" : "=l"(d) : "l"(a), "l"(b), "l"(c));
    return d;
}
__device__ __forceinline__ ull dup2(float x) {
    ull d; asm("mov.b64 %0, {%1, %1};" : "=l"(d) : "f"(x)); return d;
}
__device__ __forceinline__ ull pk2(float lo, float hi) {
    ull d; asm("mov.b64 %0, {%1, %2};" : "=l"(d) : "f"(lo), "f"(hi)); return d;
}
__device__ __forceinline__ float hadd2(ull v) {
    float lo, hi; asm("mov.b64 {%0, %1}, %2;" : "=f"(lo), "=f"(hi) : "l"(v));
    return lo + hi;
}
__device__ __forceinline__ uint32_t sa(const void* p) {
    return (uint32_t)__cvta_generic_to_shared(p);
}
__device__ __forceinline__ void mbar_wait(uint32_t mbar, unsigned parity) {
    asm volatile(
        "{\n\t.reg .pred P1;\n\t"
        "WAIT_%=:\n\t"
        "mbarrier.try_wait.parity.acquire.cta.shared::cta.b64 P1, [%0], %1;\n\t"
        "@P1 bra.uni DONE_%=;\n\t"
        "bra.uni WAIT_%=;\n\t"
        "DONE_%=:\n\t}"
        :: "r"(mbar), "r"(parity) : "memory");
}
__device__ __forceinline__ unsigned atom_add_acqrel_gpu(unsigned* p, unsigned v) {
    unsigned old;
    asm volatile("atom.add.acq_rel.gpu.global.u32 %0, [%1], %2;"
                 : "=r"(old) : "l"(p), "r"(v) : "memory");
    return old;
}
__device__ __forceinline__ void st_release_gpu(unsigned* p, unsigned v) {
    asm volatile("st.release.gpu.global.u32 [%0], %1;" :: "l"(p), "r"(v) : "memory");
}
__device__ __forceinline__ unsigned ld_acquire_gpu(const unsigned* p) {
    unsigned v;
    asm volatile("ld.acquire.gpu.global.u32 %0, [%1];" : "=r"(v) : "l"(p) : "memory");
    return v;
}
__device__ __forceinline__ void bar_arrive(int idx, unsigned target) {
    unsigned old = atom_add_acqrel_gpu(&g_cnt[idx * 32], 1u);
    if ((old & (GCTA - 1u)) == GCTA - 1u)
        st_release_gpu(&g_ph[idx * 32], target);
}
__device__ __forceinline__ void bar_poll(int idx, unsigned target) {
    while ((int)(ld_acquire_gpu(&g_ph[idx * 32]) - target) < 0) { }
}
__device__ __forceinline__ void named_bar(int id) {
    asm volatile("bar.sync %0, 128;" :: "r"(id) : "memory");
}
// stage one half (8 rows x 2KB) via bulk-async; completion -> mbar
__device__ __forceinline__ void tma_half(uint32_t mbar, uint32_t dst, const float* src) {
    asm volatile("mbarrier.arrive.expect_tx.shared.b64 _, [%0], %1;"
                 :: "r"(mbar), "r"(16384u) : "memory");
    #pragma unroll
    for (int rr = 0; rr < NBH; ++rr)
        asm volatile(
            "cp.async.bulk.shared::cta.global.mbarrier::complete_tx::bytes "
            "[%0], [%1], %2, [%3];"
            :: "r"(dst + (unsigned)(rr * HROW * 4)),
               "l"((const char*)src + rr * (HH * 4)), "r"(2048u), "r"(mbar)
            : "memory");
}

__device__ __forceinline__ float fast_sigmoid(float z) {
    return 1.f / (1.f + __expf(-z));
}
__device__ __forceinline__ float fast_tanh(float z) {
    float az = fabsf(z);
    float e  = __expf(-2.f * az);
    float t  = (1.f - e) / (1.f + e);
    return copysignf(t, z);
}

// ---------------------------------------------------------------------------
// xz kernel (VERBATIM R13, proven)
// ---------------------------------------------------------------------------
__global__ void __launch_bounds__(XZ_NTHR, 1)
xz_kernel(const float* __restrict__ x,
          const float* __restrict__ Wx,
          const float* __restrict__ bias)
{
    extern __shared__ float sm[];
    float* x_s = sm;
    float* w_s = sm + XZ_TOK * XR;

    const int tid  = threadIdx.x;
    const int tokT = blockIdx.x >> 3;
    const int colT = blockIdx.x & 7;
    const int cg   = tid >> 5;
    const int tt   = tid & 31;

    for (int c = tid; c < XZ_TOK * DD; c += XZ_NTHR) {
        int t = c >> 7, d = c & (DD - 1);
        int token = tokT * XZ_TOK + t;
        int bb = token & (BB - 1), s = token >> 6;
        x_s[t * XR + d] = x[((size_t)bb * TT + s) * DD + d];
    }
    for (int c = tid; c < DD * 256; c += XZ_NTHR) {
        int d = c >> 8, cl = c & 255;
        w_s[c] = Wx[(size_t)d * G4 + (cl >> 6) * HH + colT * 64 + (cl & 63)];
    }
    __syncthreads();

    const int hc0 = colT * 64 + cg * 8;
    ull acc[4][4];
    #pragma unroll
    for (int g = 0; g < 4; ++g)
        #pragma unroll
        for (int p = 0; p < 4; ++p)
            acc[g][p] = *(const ull*)(bias + g * HH + hc0 + 2 * p);

    const float* xr = x_s + tt * XR;
    #pragma unroll 4
    for (int d = 0; d < DD; ++d) {
        ull xd = dup2(xr[d]);
        const ull* wr = (const ull*)(w_s + d * 256 + cg * 8);
        #pragma unroll
        for (int g = 0; g < 4; ++g) {
            const ull* wg2 = wr + g * 32;
            acc[g][0] = fma2(xd, wg2[0], acc[g][0]);
            acc[g][1] = fma2(xd, wg2[1], acc[g][1]);
            acc[g][2] = fma2(xd, wg2[2], acc[g][2]);
            acc[g][3] = fma2(xd, wg2[3], acc[g][3]);
        }
    }
    int token = tokT * XZ_TOK + tt;
    int bb = token & (BB - 1), s = token >> 6;
    float v[4][8];
    #pragma unroll
    for (int g = 0; g < 4; ++g)
        #pragma unroll
        for (int p = 0; p < 4; ++p) {
            float lo, hi;
            asm("mov.b64 {%0, %1}, %2;" : "=f"(lo), "=f"(hi) : "l"(acc[g][p]));
            v[g][2 * p] = lo; v[g][2 * p + 1] = hi;
        }
    #pragma unroll
    for (int ii = 0; ii < 8; ++ii)
        g_xz4[((size_t)s * HH + hc0 + ii) * BB + bb] =
            make_float4(v[0][ii], v[1][ii], v[2][ii], v[3][ii]);
}

// ---------------------------------------------------------------------------
// One independent half-recurrence (8 rows), run by 128 threads / 4 warps.
// u: 0..127. Controller u==0 owns barrier + TMA for this half.
// ---------------------------------------------------------------------------
__device__ __forceinline__ void run_half(
    int u, int bar_id, int idx, uint32_t mbar,
    float* h_half, float* hout, const float* whsT,
    int gc, int row_base)
{
    const int r  = u & 7;                  // lane-fast -> h LDS 1 wf, xz coalesced
    const int j  = u >> 3;
    const int hc = gc * NJC + j;
    const int bb = row_base + r;
    const int wr = u >> 4, wh = u & 15;    // writeback transpose map

    const float* hr = h_half + r * HROW;
    const float* w0 = whsT + (0 * NJC + j) * WTS;
    const float* w1 = whsT + (1 * NJC + j) * WTS;
    const float* w2 = whsT + (2 * NJC + j) * WTS;
    const float* w3 = whsT + (3 * NJC + j) * WTS;

    unsigned base = 0;
    if (u == 0) {                          // prologue: h0 visible, stage h0
        base = ld_acquire_gpu(&g_ph[idx * 32]);
        bar_arrive(idx, base + 1);
        bar_poll(idx, base + 1);
        tma_half(mbar, sa(h_half), &g_h[0][row_base][0]);
    }

    float c_state = 0.f;
    for (int s = 0; s < TT; ++s) {
        float4 xzv = g_xz4[((size_t)s * HH + hc) * BB + bb];   // overlaps wait
        mbar_wait(mbar, (unsigned)(s & 1));

        ull a0 = pk2(xzv.x, 0.f), a1 = pk2(xzv.y, 0.f);
        ull a2 = pk2(xzv.z, 0.f), a3 = pk2(xzv.w, 0.f);
        #pragma unroll 4
        for (int k = 0; k < HH; k += 8) {
            ulonglong2 hA = *(const ulonglong2*)(hr + k);
            ulonglong2 hB = *(const ulonglong2*)(hr + k + 4);
            ulonglong2 wa, wb;
            wa = *(const ulonglong2*)(w0 + k); wb = *(const ulonglong2*)(w0 + k + 4);
            a0 = fma2(hA.x, wa.x, a0); a0 = fma2(hA.y, wa.y, a0);
            a0 = fma2(hB.x, wb.x, a0); a0 = fma2(hB.y, wb.y, a0);
            wa = *(const ulonglong2*)(w1 + k); wb = *(const ulonglong2*)(w1 + k + 4);
            a1 = fma2(hA.x, wa.x, a1); a1 = fma2(hA.y, wa.y, a1);
            a1 = fma2(hB.x, wb.x, a1); a1 = fma2(hB.y, wb.y, a1);
            wa = *(const ulonglong2*)(w2 + k); wb = *(const ulonglong2*)(w2 + k + 4);
            a2 = fma2(hA.x, wa.x, a2); a2 = fma2(hA.y, wa.y, a2);
            a2 = fma2(hB.x, wb.x, a2); a2 = fma2(hB.y, wb.y, a2);
            wa = *(const ulonglong2*)(w3 + k); wb = *(const ulonglong2*)(w3 + k + 4);
            a3 = fma2(hA.x, wa.x, a3); a3 = fma2(hA.y, wa.y, a3);
            a3 = fma2(hB.x, wb.x, a3); a3 = fma2(hB.y, wb.y, a3);
        }

        float zi = hadd2(a0), zf = hadd2(a1), zg = hadd2(a2), zo = hadd2(a3);
        float ig = fast_sigmoid(zi), fg = fast_sigmoid(zf);
        float gg = fast_tanh(zg),    og = fast_sigmoid(zo);
        c_state  = fg * c_state + ig * gg;
        float hn = og * fast_tanh(c_state);

        hout[r * 17 + j] = hn;
        named_bar(bar_id);
        {
            float val = hout[wr * 17 + wh];
            __stcg(&g_h[(s & 1) ^ 1][row_base + wr][gc * NJC + wh], val);
            g_hs[((size_t)(row_base + wr) * TT + s) * HH + gc * NJC + wh] = val;
        }
        named_bar(bar_id);                 // wb visible before arrive; hout reusable

        if (u == 0 && s + 1 < TT) {
            unsigned t = base + 2 + (unsigned)s;
            bar_arrive(idx, t);
            bar_poll(idx, t);
            tma_half(mbar, sa(h_half), &g_h[(s + 1) & 1][row_base][0]);
        }
    }
}

__global__ void __launch_bounds__(NTHR, 1)
group_lstm_kernel(const float* __restrict__ Wh,
                  float* __restrict__ d_cost)
{
    extern __shared__ float sm[];
    float* h_sA  = sm + HA_OFF;
    float* h_sB  = sm + HB_OFF;
    float* whsT  = sm + W_OFF;
    float* houtA = sm + HOUTA_OFF;
    float* houtB = sm + HOUTB_OFF;
    const uint32_t mbarA = sa(sm + MBAR_OFF);
    const uint32_t mbarB = sa(sm + MBAR_OFF + 2);

    const int tid  = threadIdx.x;
    const int cta  = blockIdx.x;
    const int grp  = cta >> 5;
    const int gc   = cta & 31;
    const int half = tid >> 7;
    const int u    = tid & 127;

    if (cta == 0 && tid == 0) *d_cost = 0.f;

    // stationary weights (proven layout)
    for (int i = tid; i < 64 * HH; i += NTHR) {
        int cc = i >> 9, k = i & (HH - 1);
        whsT[cc * WTS + k] = Wh[(size_t)k * G4 + (cc >> 4) * HH + gc * NJC + (cc & 15)];
    }
    // h0 zeros: 256 threads cover all 16 rows x 16 cols of this CTA
    __stcg(&g_h[0][grp * 16 + half * NBH + (u & 7)][gc * NJC + (u >> 3)], 0.f);
    if (tid == 0) {
        asm volatile("mbarrier.init.shared.b64 [%0], %1;" :: "r"(mbarA), "r"(1u) : "memory");
        asm volatile("mbarrier.init.shared.b64 [%0], %1;" :: "r"(mbarB), "r"(1u) : "memory");
    }
    __syncthreads();

    if (half == 0)
        run_half(u, 1, grp * 2,     mbarA, h_sA, houtA, whsT, gc, grp * 16);
    else
        run_half(u, 2, grp * 2 + 1, mbarB, h_sB, houtB, whsT, gc, grp * 16 + NBH);
}

// Head (VERBATIM, proven)
__global__ void __launch_bounds__(256)
head_kernel(const int* __restrict__ labels,
            const float* __restrict__ Wo,
            const float* __restrict__ bo,
            float* __restrict__ out,
            float* __restrict__ d_cost)
{
    __shared__ float part[8];
    int warp = threadIdx.x >> 5, lane = threadIdx.x & 31;
    int bt   = blockIdx.x * 8 + warp;
    const float* hrow = g_hs + (size_t)bt * HH;

    float s0 = 0.f, s1 = 0.f;
    #pragma unroll 4
    for (int k = lane; k < HH; k += 32) {
        float  h = hrow[k];
        float2 w = ((const float2*)Wo)[k];
        s0 += h * w.x; s1 += h * w.y;
    }
    #pragma unroll
    for (int off = 16; off; off >>= 1) {
        s0 += __shfl_xor_sync(0xffffffffu, s0, off);
        s1 += __shfl_xor_sync(0xffffffffu, s1, off);
    }
    if (lane == 0) {
        float l0 = s0 + bo[0], l1 = s1 + bo[1];
        float m  = fmaxf(l0, l1);
        float e0 = __expf(l0 - m), e1 = __expf(l1 - m);
        float Z  = e0 + e1;
        float inv = 1.f / Z;
        ((float2*)out)[bt] = make_float2(e0 * inv, e1 * inv);
        int lab = labels[bt];
        float llab = lab ? l1 : l0;
        part[warp] = -(llab - m - __logf(Z));
    }
    __syncthreads();
    if (threadIdx.x == 0) {
        float sum = 0.f;
        #pragma unroll
        for (int w = 0; w < 8; ++w) sum += part[w];
        atomicAdd(d_cost, sum * (1.f / (float)(BB * TT)));
    }
}

extern "C" void kernel_launch(void* const* d_in, const int* in_sizes, int n_in,
                              void* d_out, int out_size)
{
    (void)in_sizes; (void)n_in; (void)out_size;
    const float* x      = (const float*)d_in[0];
    const int*   labels = (const int*)  d_in[1];
    const float* Wx     = (const float*)d_in[2];
    const float* Wh     = (const float*)d_in[3];
    const float* b      = (const float*)d_in[4];
    const float* Wo     = (const float*)d_in[5];
    const float* bo     = (const float*)d_in[6];
    float* out    = (float*)d_out;
    float* d_cost = out + (size_t)BB * TT * NCLS;

    cudaFuncSetAttribute(xz_kernel,
                         cudaFuncAttributeMaxDynamicSharedMemorySize, XZ_SMEM_BYTES);
    cudaFuncSetAttribute(group_lstm_kernel,
                         cudaFuncAttributeMaxDynamicSharedMemorySize, SMEM_BYTES);

    xz_kernel<<<(BB * TT / XZ_TOK) * 8, XZ_NTHR, XZ_SMEM_BYTES>>>(x, Wx, b);
    group_lstm_kernel<<<NCTA, NTHR, SMEM_BYTES>>>(Wh, d_cost);
    head_kernel<<<(BB * TT) / 8, 256>>>(labels, Wo, bo, out, d_cost);
}

// round 17
// speedup vs baseline: 1.5033x; 1.2941x over previous
#include <cuda_runtime.h>
#include <cstdint>

// BinaryLSTM: B=64, T=1024, D=128, H=512, C=2
// R17 = R13 + register-blocked inner compute (4 rows x 2 cols x 4 gates per
// thread, warp = 64-wide k-chunk). Cuts smem read traffic 5 -> 1.5 B/MAC,
// attacking the 128 B/cyc/SM crossbar floor that R13-R16 were pinned at.
// TMA staging / mbar / group barrier / writeback / xz / head frozen from R13.

#define BB   64
#define TT   1024
#define DD   128
#define HH   512
#define G4   2048
#define NCLS 2
#define NCTA 128
#define NTHR 256
#define NGRP 4
#define GCTA 32
#define NBB  16       // batch rows per group / CTA
#define NJC  16       // h-cols per CTA
#define HROW 516
#define WTS  516

// smem float offsets
#define W_OFF    (NBB*HROW)                // 8256
#define ZS_OFF   (W_OFF + 64*WTS)          // 41280
#define HOUT_OFF (ZS_OFF + 8192)           // 49472  (zs: 8 kh x 256 cells x 4)
#define MBAR_OFF (HOUT_OFF + 272)          // 49744 (byte 198976, 8-aligned)
#define PB_OFF   (MBAR_OFF + 2)
#define SMEM_FLOATS (PB_OFF + 2)
#define SMEM_BYTES  (SMEM_FLOATS * 4)      // ~199 KB

// xz kernel (verbatim R13, proven)
#define XZ_TOK  32
#define XR      129
#define XZ_NTHR 256
#define XZ_SMEM_FLOATS (XZ_TOK*XR + DD*256)
#define XZ_SMEM_BYTES  (XZ_SMEM_FLOATS * 4)

typedef unsigned long long ull;

// ---- device scratch ----
__device__ float  g_h[2][BB][HH];
__device__ float  g_hs[(size_t)BB * TT * HH];
__device__ float4 g_xz4[(size_t)BB * TT * HH];   // [s][hc][bb] -> (i,f,g,o)
__device__ unsigned g_cnt[NGRP * 32];
__device__ unsigned g_ph [NGRP * 32];

// ---- PTX helpers ----
__device__ __forceinline__ ull fma2(ull a, ull b, ull c) {
    ull d; asm("fma.rn.f32x2 %0, %1, %2, %3;" : "=l"(d) : "l"(a), "l"(b), "l"(c));
    return d;
}
__device__ __forceinline__ ull dup2(float x) {
    ull d; asm("mov.b64 %0, {%1, %1};" : "=l"(d) : "f"(x)); return d;
}
__device__ __forceinline__ float hadd2(ull v) {
    float lo, hi; asm("mov.b64 {%0, %1}, %2;" : "=f"(lo), "=f"(hi) : "l"(v));
    return lo + hi;
}
__device__ __forceinline__ uint32_t sa(const void* p) {
    return (uint32_t)__cvta_generic_to_shared(p);
}
__device__ __forceinline__ void mbar_wait(uint32_t mbar, unsigned parity) {
    asm volatile(
        "{\n\t.reg .pred P1;\n\t"
        "WAIT_%=:\n\t"
        "mbarrier.try_wait.parity.acquire.cta.shared::cta.b64 P1, [%0], %1;\n\t"
        "@P1 bra.uni DONE_%=;\n\t"
        "bra.uni WAIT_%=;\n\t"
        "DONE_%=:\n\t}"
        :: "r"(mbar), "r"(parity) : "memory");
}
__device__ __forceinline__ unsigned atom_add_acqrel_gpu(unsigned* p, unsigned v) {
    unsigned old;
    asm volatile("atom.add.acq_rel.gpu.global.u32 %0, [%1], %2;"
                 : "=r"(old) : "l"(p), "r"(v) : "memory");
    return old;
}
__device__ __forceinline__ void st_release_gpu(unsigned* p, unsigned v) {
    asm volatile("st.release.gpu.global.u32 [%0], %1;" :: "l"(p), "r"(v) : "memory");
}
__device__ __forceinline__ unsigned ld_acquire_gpu(const unsigned* p) {
    unsigned v;
    asm volatile("ld.acquire.gpu.global.u32 %0, [%1];" : "=r"(v) : "l"(p) : "memory");
    return v;
}
__device__ __forceinline__ void group_barrier(unsigned target, int grp) {
    __syncthreads();
    if (threadIdx.x == 0) {
        unsigned old = atom_add_acqrel_gpu(&g_cnt[grp * 32], 1u);
        if ((old & (GCTA - 1u)) == GCTA - 1u)
            st_release_gpu(&g_ph[grp * 32], target);
        while ((int)(ld_acquire_gpu(&g_ph[grp * 32]) - target) < 0) { }
    }
    __syncthreads();
}

__device__ __forceinline__ float fast_sigmoid(float z) {
    return 1.f / (1.f + __expf(-z));
}
__device__ __forceinline__ float fast_tanh(float z) {
    float az = fabsf(z);
    float e  = __expf(-2.f * az);
    float t  = (1.f - e) / (1.f + e);
    return copysignf(t, z);
}

// ---------------------------------------------------------------------------
// xz kernel (VERBATIM R13, proven)
// ---------------------------------------------------------------------------
__global__ void __launch_bounds__(XZ_NTHR, 1)
xz_kernel(const float* __restrict__ x,
          const float* __restrict__ Wx,
          const float* __restrict__ bias)
{
    extern __shared__ float sm[];
    float* x_s = sm;
    float* w_s = sm + XZ_TOK * XR;

    const int tid  = threadIdx.x;
    const int tokT = blockIdx.x >> 3;
    const int colT = blockIdx.x & 7;
    const int cg   = tid >> 5;
    const int tt   = tid & 31;

    for (int c = tid; c < XZ_TOK * DD; c += XZ_NTHR) {
        int t = c >> 7, d = c & (DD - 1);
        int token = tokT * XZ_TOK + t;
        int bb = token & (BB - 1), s = token >> 6;
        x_s[t * XR + d] = x[((size_t)bb * TT + s) * DD + d];
    }
    for (int c = tid; c < DD * 256; c += XZ_NTHR) {
        int d = c >> 8, cl = c & 255;
        w_s[c] = Wx[(size_t)d * G4 + (cl >> 6) * HH + colT * 64 + (cl & 63)];
    }
    __syncthreads();

    const int hc0 = colT * 64 + cg * 8;
    ull acc[4][4];
    #pragma unroll
    for (int g = 0; g < 4; ++g)
        #pragma unroll
        for (int p = 0; p < 4; ++p)
            acc[g][p] = *(const ull*)(bias + g * HH + hc0 + 2 * p);

    const float* xr = x_s + tt * XR;
    #pragma unroll 4
    for (int d = 0; d < DD; ++d) {
        ull xd = dup2(xr[d]);
        const ull* wr = (const ull*)(w_s + d * 256 + cg * 8);
        #pragma unroll
        for (int g = 0; g < 4; ++g) {
            const ull* wg2 = wr + g * 32;
            acc[g][0] = fma2(xd, wg2[0], acc[g][0]);
            acc[g][1] = fma2(xd, wg2[1], acc[g][1]);
            acc[g][2] = fma2(xd, wg2[2], acc[g][2]);
            acc[g][3] = fma2(xd, wg2[3], acc[g][3]);
        }
    }
    int token = tokT * XZ_TOK + tt;
    int bb = token & (BB - 1), s = token >> 6;
    float v[4][8];
    #pragma unroll
    for (int g = 0; g < 4; ++g)
        #pragma unroll
        for (int p = 0; p < 4; ++p) {
            float lo, hi;
            asm("mov.b64 {%0, %1}, %2;" : "=f"(lo), "=f"(hi) : "l"(acc[g][p]));
            v[g][2 * p] = lo; v[g][2 * p + 1] = hi;
        }
    #pragma unroll
    for (int ii = 0; ii < 8; ++ii)
        g_xz4[((size_t)s * HH + hc0 + ii) * BB + bb] =
            make_float4(v[0][ii], v[1][ii], v[2][ii], v[3][ii]);
}

// ---------------------------------------------------------------------------
// Group recurrence with register-blocked inner compute.
// Compute role: warp kh = tid>>5 owns k in [kh*64, kh*64+64);
//   lane blk = tid&31 -> rq = blk&3 (row quad), jb = blk>>2 (col pair).
//   Thread accumulates 4 rows x 2 cols x 4 gates over its 64 k.
// Combine role: thread tid -> cell (bb_l = tid&15, j = tid>>4); zs address is
//   exactly zs[kh*1024 + tid*4] (conflict-free float4).
// ---------------------------------------------------------------------------
__global__ void __launch_bounds__(NTHR, 1)
group_lstm_kernel(const float* __restrict__ Wh,
                  float* __restrict__ d_cost)
{
    extern __shared__ float sm[];
    float* h_s  = sm;                          // [16][HROW]
    float* whsT = sm + W_OFF;                  // [64][WTS]  cc = g*16 + jc
    float* zs   = sm + ZS_OFF;                 // [8][256][4]
    float* hout = sm + HOUT_OFF;               // [16][17]
    const uint32_t mbar = sa(sm + MBAR_OFF);
    unsigned* pb = (unsigned*)(sm + PB_OFF);

    const int tid  = threadIdx.x;
    const int cta  = blockIdx.x;
    const int grp  = cta >> 5;
    const int gc   = cta & 31;
    // compute role
    const int kh = tid >> 5;
    const int blk = tid & 31;
    const int rq = blk & 3;
    const int jb = blk >> 2;
    const int k0 = kh * 64;
    // combine role
    const int bb_l = tid & 15;
    const int j    = tid >> 4;
    const int bb   = grp * NBB + bb_l;
    const int hc   = gc * NJC + j;

    if (cta == 0 && tid == 0) *d_cost = 0.f;

    for (int i = tid; i < 64 * HH; i += NTHR) {
        int cc = i >> 9, k = i & (HH - 1);
        whsT[cc * WTS + k] = Wh[(size_t)k * G4 + (cc >> 4) * HH + gc * NJC + (cc & 15)];
    }
    if (tid == 0) {
        *pb = ld_acquire_gpu(&g_ph[grp * 32]);
        asm volatile("mbarrier.init.shared.b64 [%0], %1;" :: "r"(mbar), "r"(1u) : "memory");
    }
    __stcg(&g_h[0][bb][hc], 0.f);
    __syncthreads();
    unsigned gb_t = *pb;

    group_barrier(++gb_t, grp);               // group h0 visible

    // compute-role pointers
    const float* hp0 = h_s + (rq * 4 + 0) * HROW + k0;
    const float* hp1 = h_s + (rq * 4 + 1) * HROW + k0;
    const float* hp2 = h_s + (rq * 4 + 2) * HROW + k0;
    const float* hp3 = h_s + (rq * 4 + 3) * HROW + k0;
    const float* wp[2][4];
    #pragma unroll
    for (int c = 0; c < 2; ++c)
        #pragma unroll
        for (int g = 0; g < 4; ++g)
            wp[c][g] = whsT + (g * NJC + jb * 2 + c) * WTS + k0;
    float* zw = zs + kh * 1024;

    float c_state = 0.f;
    int cur = 0;
    for (int s = 0; s < TT; ++s) {
        if (tid == 0) {
            asm volatile("mbarrier.arrive.expect_tx.shared.b64 _, [%0], %1;"
                         :: "r"(mbar), "r"(32768u) : "memory");
            const char* hg = (const char*)&g_h[cur][grp * NBB][0];
            #pragma unroll
            for (int rr = 0; rr < NBB; ++rr)
                asm volatile(
                    "cp.async.bulk.shared::cta.global.mbarrier::complete_tx::bytes "
                    "[%0], [%1], %2, [%3];"
                    :: "r"(sa(h_s) + (unsigned)(rr * HROW * 4)),
                       "l"(hg + rr * (HH * 4)), "r"(2048u), "r"(mbar) : "memory");
        }
        float4 xzv = g_xz4[((size_t)s * HH + hc) * BB + bb];   // overlaps wait
        mbar_wait(mbar, (unsigned)(s & 1));

        // ---- register-blocked partial dots: acc[c][g][r] over 64 k ----
        ull acc[2][4][4];
        #pragma unroll
        for (int c = 0; c < 2; ++c)
            #pragma unroll
            for (int g = 0; g < 4; ++g)
                #pragma unroll
                for (int r = 0; r < 4; ++r) acc[c][g][r] = 0;

        #pragma unroll
        for (int kk = 0; kk < 64; kk += 8) {
            ulonglong2 hA0 = *(const ulonglong2*)(hp0 + kk);
            ulonglong2 hB0 = *(const ulonglong2*)(hp0 + kk + 4);
            ulonglong2 hA1 = *(const ulonglong2*)(hp1 + kk);
            ulonglong2 hB1 = *(const ulonglong2*)(hp1 + kk + 4);
            ulonglong2 hA2 = *(const ulonglong2*)(hp2 + kk);
            ulonglong2 hB2 = *(const ulonglong2*)(hp2 + kk + 4);
            ulonglong2 hA3 = *(const ulonglong2*)(hp3 + kk);
            ulonglong2 hB3 = *(const ulonglong2*)(hp3 + kk + 4);
            #pragma unroll
            for (int c = 0; c < 2; ++c)
                #pragma unroll
                for (int g = 0; g < 4; ++g) {
                    ulonglong2 wa = *(const ulonglong2*)(wp[c][g] + kk);
                    ulonglong2 wb = *(const ulonglong2*)(wp[c][g] + kk + 4);
                    acc[c][g][0] = fma2(hA0.x, wa.x, acc[c][g][0]);
                    acc[c][g][0] = fma2(hA0.y, wa.y, acc[c][g][0]);
                    acc[c][g][0] = fma2(hB0.x, wb.x, acc[c][g][0]);
                    acc[c][g][0] = fma2(hB0.y, wb.y, acc[c][g][0]);
                    acc[c][g][1] = fma2(hA1.x, wa.x, acc[c][g][1]);
                    acc[c][g][1] = fma2(hA1.y, wa.y, acc[c][g][1]);
                    acc[c][g][1] = fma2(hB1.x, wb.x, acc[c][g][1]);
                    acc[c][g][1] = fma2(hB1.y, wb.y, acc[c][g][1]);
                    acc[c][g][2] = fma2(hA2.x, wa.x, acc[c][g][2]);
                    acc[c][g][2] = fma2(hA2.y, wa.y, acc[c][g][2]);
                    acc[c][g][2] = fma2(hB2.x, wb.x, acc[c][g][2]);
                    acc[c][g][2] = fma2(hB2.y, wb.y, acc[c][g][2]);
                    acc[c][g][3] = fma2(hA3.x, wa.x, acc[c][g][3]);
                    acc[c][g][3] = fma2(hA3.y, wa.y, acc[c][g][3]);
                    acc[c][g][3] = fma2(hB3.x, wb.x, acc[c][g][3]);
                    acc[c][g][3] = fma2(hB3.y, wb.y, acc[c][g][3]);
                }
        }
        // partials -> zs[kh][ (jc*16 + row) ] as float4 (i,f,g,o)
        #pragma unroll
        for (int c = 0; c < 2; ++c)
            #pragma unroll
            for (int r = 0; r < 4; ++r) {
                int cell = (jb * 2 + c) * 16 + rq * 4 + r;
                *(float4*)(zw + cell * 4) =
                    make_float4(hadd2(acc[c][0][r]), hadd2(acc[c][1][r]),
                                hadd2(acc[c][2][r]), hadd2(acc[c][3][r]));
            }
        __syncthreads();

        // ---- combine: thread tid owns cell (bb_l, j); zs addr = tid*16B ----
        float4 zsum = *(const float4*)(zs + tid * 4);
        #pragma unroll
        for (int q = 1; q < 8; ++q) {
            float4 p = *(const float4*)(zs + q * 1024 + tid * 4);
            zsum.x += p.x; zsum.y += p.y; zsum.z += p.z; zsum.w += p.w;
        }
        float zi = zsum.x + xzv.x, zf = zsum.y + xzv.y;
        float zg = zsum.z + xzv.z, zo = zsum.w + xzv.w;
        float ig = fast_sigmoid(zi), fg = fast_sigmoid(zf);
        float gg = fast_tanh(zg),    og = fast_sigmoid(zo);
        c_state  = fg * c_state + ig * gg;
        float hn = og * fast_tanh(c_state);

        hout[bb_l * 17 + j] = hn;
        __syncthreads();
        {
            int b2 = tid >> 4, h2 = tid & 15;
            float val = hout[b2 * 17 + h2];
            __stcg(&g_h[cur ^ 1][grp * NBB + b2][gc * NJC + h2], val);
            g_hs[((size_t)(grp * NBB + b2) * TT + s) * HH + gc * NJC + h2] = val;
        }

        group_barrier(++gb_t, grp);
        cur ^= 1;
    }
}

// Head (VERBATIM, proven)
__global__ void __launch_bounds__(256)
head_kernel(const int* __restrict__ labels,
            const float* __restrict__ Wo,
            const float* __restrict__ bo,
            float* __restrict__ out,
            float* __restrict__ d_cost)
{
    __shared__ float part[8];
    int warp = threadIdx.x >> 5, lane = threadIdx.x & 31;
    int bt   = blockIdx.x * 8 + warp;
    const float* hrow = g_hs + (size_t)bt * HH;

    float s0 = 0.f, s1 = 0.f;
    #pragma unroll 4
    for (int k = lane; k < HH; k += 32) {
        float  h = hrow[k];
        float2 w = ((const float2*)Wo)[k];
        s0 += h * w.x; s1 += h * w.y;
    }
    #pragma unroll
    for (int off = 16; off; off >>= 1) {
        s0 += __shfl_xor_sync(0xffffffffu, s0, off);
        s1 += __shfl_xor_sync(0xffffffffu, s1, off);
    }
    if (lane == 0) {
        float l0 = s0 + bo[0], l1 = s1 + bo[1];
        float m  = fmaxf(l0, l1);
        float e0 = __expf(l0 - m), e1 = __expf(l1 - m);
        float Z  = e0 + e1;
        float inv = 1.f / Z;
        ((float2*)out)[bt] = make_float2(e0 * inv, e1 * inv);
        int lab = labels[bt];
        float llab = lab ? l1 : l0;
        part[warp] = -(llab - m - __logf(Z));
    }
    __syncthreads();
    if (threadIdx.x == 0) {
        float sum = 0.f;
        #pragma unroll
        for (int w = 0; w < 8; ++w) sum += part[w];
        atomicAdd(d_cost, sum * (1.f / (float)(BB * TT)));
    }
}

extern "C" void kernel_launch(void* const* d_in, const int* in_sizes, int n_in,
                              void* d_out, int out_size)
{
    (void)in_sizes; (void)n_in; (void)out_size;
    const float* x      = (const float*)d_in[0];
    const int*   labels = (const int*)  d_in[1];
    const float* Wx     = (const float*)d_in[2];
    const float* Wh     = (const float*)d_in[3];
    const float* b      = (const float*)d_in[4];
    const float* Wo     = (const float*)d_in[5];
    const float* bo     = (const float*)d_in[6];
    float* out    = (float*)d_out;
    float* d_cost = out + (size_t)BB * TT * NCLS;

    cudaFuncSetAttribute(xz_kernel,
                         cudaFuncAttributeMaxDynamicSharedMemorySize, XZ_SMEM_BYTES);
    cudaFuncSetAttribute(group_lstm_kernel,
                         cudaFuncAttributeMaxDynamicSharedMemorySize, SMEM_BYTES);

    xz_kernel<<<(BB * TT / XZ_TOK) * 8, XZ_NTHR, XZ_SMEM_BYTES>>>(x, Wx, b);
    group_lstm_kernel<<<NCTA, NTHR, SMEM_BYTES>>>(Wh, d_cost);
    head_kernel<<<(BB * TT) / 8, 256>>>(labels, Wo, bo, out, d_cost);
}